// round 12
// baseline (speedup 1.0000x reference)
#include <cuda_runtime.h>
#include <cuda_bf16.h>

#define Bb 128
#define Tt 256
#define Hh 512
#define Ee 300
#define Vv 50000
#define FH 2048
#define NCTA 128

// lstm smem offsets
#define W0F_OFF 0
#define W1F_OFF 32768
#define DSM0_OFF 98304
#define DSM1_OFF 106752
#define DSM0B_OFF 115264
#define DSM1B_OFF 123712
#define BIAS_OFF 132160
#define SMEM_BYTES 132224

// gemm_in smem offsets
#define GI_ROWS_OFF 0
#define GI_WF_OFF 1024
#define GI_DSM_OFF 66560
#define GI_SMEM_BYTES 100352

// ---------------- globals ----------------
__device__ float g_G0in[(size_t)Tt * FH * Bb];   // [t][gatecol][b]
// h planes in A-fragment layout (validated R6/R7):
//   uint4 idx = kt*256 + wm*32 + lane; row=wm*16+(lane>>2), kp=kt*8+(lane&3)
__device__ __align__(16) unsigned char g_h0hi[2][131072];
__device__ __align__(16) unsigned char g_h0lo[2][131072];
__device__ __align__(16) unsigned char g_h1hi[2][131072];
__device__ __align__(16) unsigned char g_h1lo[2][131072];
__device__ float g_h1f[Hh * Bb];
__device__ int g_x64;
__device__ unsigned g_slots[NCTA];
__device__ volatile unsigned g_rel;

// ---------------- helpers ----------------
__device__ __forceinline__ float ex2f(float x) { float y; asm("ex2.approx.f32 %0, %1;" : "=f"(y) : "f"(x)); return y; }
__device__ __forceinline__ float rcpf(float x) { float y; asm("rcp.approx.f32 %0, %1;" : "=f"(y) : "f"(x)); return y; }
__device__ __forceinline__ float sigm(float x) { return rcpf(1.0f + ex2f(-1.4426950408889634f * x)); }
__device__ __forceinline__ float tanh_(float x) { return fmaf(2.0f, sigm(2.0f * x), -1.0f); }
__device__ __forceinline__ unsigned short bfr(float f) {
    unsigned short u; asm("cvt.rn.bf16.f32 %0, %1;" : "=h"(u) : "f"(f)); return u;
}
__device__ __forceinline__ float bf2f(unsigned short u) {
    return __uint_as_float((unsigned)u << 16);
}
// split two floats into packed-bf16 hi and lo planes
__device__ __forceinline__ void split2(float a, float b, unsigned& hi, unsigned& lo) {
    unsigned short ha = bfr(a), hb = bfr(b);
    hi = (unsigned)ha | ((unsigned)hb << 16);
    lo = (unsigned)bfr(a - bf2f(ha)) | ((unsigned)bfr(b - bf2f(hb)) << 16);
}

__device__ __forceinline__ void mma_bf16(float d[4], const uint4& a, unsigned b0, unsigned b1) {
    asm volatile("mma.sync.aligned.m16n8k16.row.col.f32.bf16.bf16.f32 "
        "{%0,%1,%2,%3}, {%4,%5,%6,%7}, {%8,%9}, {%0,%1,%2,%3};"
        : "+f"(d[0]), "+f"(d[1]), "+f"(d[2]), "+f"(d[3])
        : "r"(a.x), "r"(a.y), "r"(a.z), "r"(a.w), "r"(b0), "r"(b1));
}

// slot barrier (validated R8/R9): parallel arrivals, CTA0 collects, single release
__device__ __forceinline__ void grid_sync(unsigned gen) {
    __syncthreads();
    if (threadIdx.x == 0) {
        __threadfence();
        ((volatile unsigned*)g_slots)[blockIdx.x] = gen;
    }
    if (blockIdx.x == 0) {
        if (threadIdx.x < NCTA) {
            while (((volatile unsigned*)g_slots)[threadIdx.x] < gen) { }
            __threadfence();
        }
        __syncthreads();
        if (threadIdx.x == 0) g_rel = gen;
    } else {
        if (threadIdx.x == 0) {
            while (g_rel < gen) { }
            __threadfence();
        }
    }
    __syncthreads();
}

// ---------------- detect / reset ----------------
__global__ void detect_kernel(const void* x) {
    const long long* p = (const long long*)x;
    int ok64 = 1;
    for (int i = 0; i < 16; i++) { long long v = p[i]; if (v < 0 || v >= Vv) ok64 = 0; }
    g_x64 = ok64;
}
__device__ __forceinline__ int token_at(const void* x, int idx) {
    if (g_x64) return (int)((const long long*)x)[idx];
    return ((const int*)x)[idx];
}
__global__ void reset_kernel() {
    for (int i = 0; i < NCTA; i++) g_slots[i] = 0;
    g_rel = 0;
}

// ---------------- G0in precompute: warp-MMA bf16 3-term (validated R9) ----------------
__global__ void __launch_bounds__(512) gemm_in_mma(
    const void* __restrict__ x, const float* __restrict__ emb,
    const float* __restrict__ W0, const float* __restrict__ b0)
{
    extern __shared__ char smg[];
    int* rows = (int*)(smg + GI_ROWS_OFF);
    uint4* wf = (uint4*)(smg + GI_WF_OFF);
    float* dsmA = (float*)(smg + GI_DSM_OFF);
    float* dsmB = (float*)(smg + GI_DSM_OFF + 16896);

    const int tid = threadIdx.x;
    const int bx = blockIdx.x;
    const int t = blockIdx.y;
    const int wid = tid >> 5;
    const int lane = tid & 31;
    const int wm = wid & 7;
    const int nh = wid >> 3;

    if (tid < 128) rows[tid] = token_at(x, tid * Tt + t);

    auto build_w = [&](int kc, int buf) {
        int nkt = (kc == 4) ? 3 : 4;
        uint4* dst = wf + buf * 2048;
        for (int e = tid; e < nkt * 512; e += 512) {
            int j = e >> 9, cg = (e >> 5) & 15, ln = e & 31;
            int col = bx * 128 + cg * 8 + (ln >> 2);
            int k = (kc * 4 + j) * 16 + (ln & 3) * 2;
            float v0 = (k     < Ee) ? W0[(size_t)k * FH + col]       : 0.f;
            float v1 = (k + 1 < Ee) ? W0[(size_t)(k + 1) * FH + col] : 0.f;
            float v8 = (k + 8 < Ee) ? W0[(size_t)(k + 8) * FH + col] : 0.f;
            float v9 = (k + 9 < Ee) ? W0[(size_t)(k + 9) * FH + col] : 0.f;
            unsigned h01, l01, h89, l89;
            split2(v0, v1, h01, l01);
            split2(v8, v9, h89, l89);
            dst[(j * 16 + cg) * 32 + ln] = make_uint4(h01, h89, l01, l89);
        }
    };

    __syncthreads();
    build_w(0, 0);
    __syncthreads();

    float d[8][4];
#pragma unroll
    for (int n = 0; n < 8; n++)
#pragma unroll
        for (int q = 0; q < 4; q++) d[n][q] = 0.f;

    const int r1 = wm * 16 + (lane >> 2);
    const int r2 = r1 + 8;
    const float* e1 = emb + (size_t)rows[r1] * Ee;
    const float* e2 = emb + (size_t)rows[r2] * Ee;

    for (int kc = 0; kc < 5; kc++) {
        int nkt = (kc == 4) ? 3 : 4;
        uint4 Ah[4], Al[4];
        for (int j = 0; j < nkt; j++) {
            int k = (kc * 4 + j) * 16 + (lane & 3) * 2;
            float a0 = (k     < Ee) ? e1[k]     : 0.f;
            float a1 = (k + 1 < Ee) ? e1[k + 1] : 0.f;
            float b0v = (k     < Ee) ? e2[k]     : 0.f;
            float b1v = (k + 1 < Ee) ? e2[k + 1] : 0.f;
            float c0 = (k + 8 < Ee) ? e1[k + 8] : 0.f;
            float c1 = (k + 9 < Ee) ? e1[k + 9] : 0.f;
            float f0 = (k + 8 < Ee) ? e2[k + 8] : 0.f;
            float f1 = (k + 9 < Ee) ? e2[k + 9] : 0.f;
            unsigned xh, xl, yh, yl, zh, zl, wh, wl;
            split2(a0, a1, xh, xl);
            split2(b0v, b1v, yh, yl);
            split2(c0, c1, zh, zl);
            split2(f0, f1, wh, wl);
            Ah[j] = make_uint4(xh, yh, zh, wh);
            Al[j] = make_uint4(xl, yl, zl, wl);
        }
        const uint4* wcur = wf + (kc & 1) * 2048;
        for (int j = 0; j < nkt; j++) {
#pragma unroll
            for (int nt = 0; nt < 8; nt++) {
                uint4 w = wcur[(j * 16 + nh * 8 + nt) * 32 + lane];
                mma_bf16(d[nt], Ah[j], w.x, w.y);
                mma_bf16(d[nt], Al[j], w.x, w.y);
                mma_bf16(d[nt], Ah[j], w.z, w.w);
            }
        }
        if (kc < 4) build_w(kc + 1, (kc + 1) & 1);
        __syncthreads();
    }

    const int r0 = wm * 16 + (lane >> 2);
    for (int p = 0; p < 2; p++) {
        float* mybuf = nh ? dsmB : dsmA;
#pragma unroll
        for (int q = 0; q < 4; q++) {
            int nt = p * 4 + q;
            int lc = q * 8 + (lane & 3) * 2;
            mybuf[lc * 132 + r0]           = d[nt][0];
            mybuf[(lc + 1) * 132 + r0]     = d[nt][1];
            mybuf[lc * 132 + r0 + 8]       = d[nt][2];
            mybuf[(lc + 1) * 132 + r0 + 8] = d[nt][3];
        }
        __syncthreads();
#pragma unroll
        for (int it = 0; it < 16; it++) {
            int e = it * 512 + tid;
            int col64 = e >> 7, row = e & 127;
            int half = col64 >> 5, c5 = col64 & 31;
            int gcol = bx * 128 + half * 64 + p * 32 + c5;
            float v = (half ? dsmB : dsmA)[c5 * 132 + row] + b0[gcol];
            g_G0in[((size_t)t * FH + gcol) * Bb + row] = v;
        }
        __syncthreads();
    }
}

// ---------------- persistent warp-MMA LSTM ----------------
__global__ void __launch_bounds__(512, 1) lstm_mma(
    const float* __restrict__ W0, const float* __restrict__ W1,
    const float* __restrict__ b1, const float* __restrict__ Wd,
    const float* __restrict__ bd, float* __restrict__ out)
{
    extern __shared__ char smc[];
    uint4* w0f = (uint4*)(smc + W0F_OFF);
    uint4* w1f = (uint4*)(smc + W1F_OFF);
    float* dsm0 = (float*)(smc + DSM0_OFF);
    float* dsm1 = (float*)(smc + DSM1_OFF);
    float* dsm0b = (float*)(smc + DSM0B_OFF);
    float* dsm1b = (float*)(smc + DSM1B_OFF);
    float* bias1s = (float*)(smc + BIAS_OFF);

    const int tid = threadIdx.x;
    const int cta = blockIdx.x;
    const int cell0 = cta * 4;
    const int wid = tid >> 5;
    const int lane = tid & 31;
    const int kh = wid >> 3;
    const int wm = wid & 7;

    // ---- build W fragments (once; validated) ----
    for (int idx = tid; idx < 2048; idx += 512) {
        int kt = idx >> 6, nt = (idx >> 5) & 1, ln = idx & 31;
        int col = nt * 8 + (ln >> 2);
        int gcol = (col >> 2) * 512 + cell0 + (col & 3);
        int kb = kt * 16 + (ln & 3) * 2;
        float v0 = W0[(size_t)(Ee + kb) * FH + gcol];
        float v1 = W0[(size_t)(Ee + kb + 1) * FH + gcol];
        float v8 = W0[(size_t)(Ee + kb + 8) * FH + gcol];
        float v9 = W0[(size_t)(Ee + kb + 9) * FH + gcol];
        unsigned h01, l01, h89, l89;
        split2(v0, v1, h01, l01);
        split2(v8, v9, h89, l89);
        w0f[idx] = make_uint4(h01, h89, l01, l89);
    }
    for (int idx = tid; idx < 4096; idx += 512) {
        int kt = idx >> 6, nt = (idx >> 5) & 1, ln = idx & 31;
        int col = nt * 8 + (ln >> 2);
        int gcol = (col >> 2) * 512 + cell0 + (col & 3);
        int kb = kt * 16 + (ln & 3) * 2;
        float v0 = W1[(size_t)kb * FH + gcol];
        float v1 = W1[(size_t)(kb + 1) * FH + gcol];
        float v8 = W1[(size_t)(kb + 8) * FH + gcol];
        float v9 = W1[(size_t)(kb + 9) * FH + gcol];
        unsigned h01, l01, h89, l89;
        split2(v0, v1, h01, l01);
        split2(v8, v9, h89, l89);
        w1f[idx] = make_uint4(h01, h89, l01, l89);
    }
    if (tid < 16) bias1s[tid] = b1[(tid >> 2) * 512 + cell0 + (tid & 3)];

    {
        int o = cta * 512 + tid;
        if (o < 8192) {
            uint4 z = make_uint4(0, 0, 0, 0);
            ((uint4*)g_h0hi[1])[o] = z; ((uint4*)g_h0lo[1])[o] = z;
            ((uint4*)g_h1hi[1])[o] = z; ((uint4*)g_h1lo[1])[o] = z;
        }
    }
    unsigned gen = 1;
    grid_sync(gen);

    // epilogue mapping (validated R7)
    const int row = tid & 127;
    const int u = tid >> 7;
    const int kp_g = (cell0 + u) >> 1;
    const int half = u & 1;
    const int kt_e = kp_g >> 3, kpi = kp_g & 7;
    const int rr = row & 15;
    const unsigned eoff = (unsigned)(kt_e * 4096 + (row >> 4) * 512 +
                          (((rr & 7) << 2) | (kpi & 3)) * 16 +
                          ((kpi >= 4 ? 2 : 0) + (rr >= 8 ? 1 : 0)) * 4 + half * 2);
    float c0r = 0.f, c1r = 0.f;

    const unsigned fbase = wm * 32 + lane;
    const unsigned kbase = kh * 16;

    for (int i = 0; i <= Tt; i++) {
        const int pA = (i + 1) & 1;
        const int pW = i & 1;
        const bool doL0 = (i < Tt);
        const bool doL1 = (i > 0);

        float g0v[4];
        if (doL0) {
#pragma unroll
            for (int g = 0; g < 4; g++)
                g0v[g] = __ldcg(&g_G0in[((size_t)i * FH + g * 512 + cell0 + u) * Bb + row]);
        }

        float d0[2][4], d1[2][4];
#pragma unroll
        for (int n = 0; n < 2; n++)
#pragma unroll
            for (int q = 0; q < 4; q++) { d0[n][q] = 0.f; d1[n][q] = 0.f; }

        // ---- unified 32-unit pipeline: units 0..15 = h0(i-1), 16..31 = h1(i-1) ----
        {
            const uint4* ah0 = (const uint4*)g_h0hi[pA] + fbase;
            const uint4* al0 = (const uint4*)g_h0lo[pA] + fbase;
            const uint4* ah1 = (const uint4*)g_h1hi[pW] + fbase;
            const uint4* al1 = (const uint4*)g_h1lo[pW] + fbase;
            uint4 A[2][4], L[2][4];
#pragma unroll
            for (int j = 0; j < 4; j++) {
                A[0][j] = __ldcg(ah0 + (kbase + j) * 256);
                L[0][j] = __ldcg(al0 + (kbase + j) * 256);
            }
#pragma unroll
            for (int kb = 0; kb < 8; kb++) {
                const int cur = kb & 1, nxt = cur ^ 1;
                if (kb < 7) {
#pragma unroll
                    for (int j = 0; j < 4; j++) {
                        const int w = (kb + 1) * 4 + j;
                        if (w < 16) {
                            A[nxt][j] = __ldcg(ah0 + (kbase + w) * 256);
                            L[nxt][j] = __ldcg(al0 + (kbase + w) * 256);
                        } else {
                            A[nxt][j] = __ldcg(ah1 + (kbase + w - 16) * 256);
                            L[nxt][j] = __ldcg(al1 + (kbase + w - 16) * 256);
                        }
                    }
                }
#pragma unroll
                for (int j = 0; j < 4; j++) {
                    const int w = kb * 4 + j;
                    if (w < 16) {
                        const int kt = kbase + w;
#pragma unroll
                        for (int nt = 0; nt < 2; nt++) {
                            if (doL0) {
                                uint4 wt = w0f[(kt * 2 + nt) * 32 + lane];
                                mma_bf16(d0[nt], A[cur][j], wt.x, wt.y);
                                mma_bf16(d0[nt], L[cur][j], wt.x, wt.y);
                                mma_bf16(d0[nt], A[cur][j], wt.z, wt.w);
                            }
                            if (doL1) {
                                uint4 wt = w1f[(kt * 2 + nt) * 32 + lane];
                                mma_bf16(d1[nt], A[cur][j], wt.x, wt.y);
                                mma_bf16(d1[nt], L[cur][j], wt.x, wt.y);
                                mma_bf16(d1[nt], A[cur][j], wt.z, wt.w);
                            }
                        }
                    } else {
                        if (doL1) {
                            const int kt = kbase + w - 16;
#pragma unroll
                            for (int nt = 0; nt < 2; nt++) {
                                uint4 wt = w1f[((32 + kt) * 2 + nt) * 32 + lane];
                                mma_bf16(d1[nt], A[cur][j], wt.x, wt.y);
                                mma_bf16(d1[nt], L[cur][j], wt.x, wt.y);
                                mma_bf16(d1[nt], A[cur][j], wt.z, wt.w);
                            }
                        }
                    }
                }
            }
        }

        // ---- combine: each K-half writes its OWN buffers; ONE sync (validated R9) ----
        {
            int r0 = wm * 16 + (lane >> 2);
            float* b0p = kh ? dsm0b : dsm0;
            float* b1p = kh ? dsm1b : dsm1;
#pragma unroll
            for (int nt = 0; nt < 2; nt++) {
                int c = nt * 8 + (lane & 3) * 2;
                b0p[c * 132 + r0]           = d0[nt][0];
                b0p[(c + 1) * 132 + r0]     = d0[nt][1];
                b0p[c * 132 + r0 + 8]       = d0[nt][2];
                b0p[(c + 1) * 132 + r0 + 8] = d0[nt][3];
                b1p[c * 132 + r0]           = d1[nt][0];
                b1p[(c + 1) * 132 + r0]     = d1[nt][1];
                b1p[c * 132 + r0 + 8]       = d1[nt][2];
                b1p[(c + 1) * 132 + r0 + 8] = d1[nt][3];
            }
        }
        __syncthreads();

        // ---- L0 epilogue ----
        if (doL0) {
            float gi = dsm0[(0  + u) * 132 + row] + dsm0b[(0  + u) * 132 + row] + g0v[0];
            float gj = dsm0[(4  + u) * 132 + row] + dsm0b[(4  + u) * 132 + row] + g0v[1];
            float gf = dsm0[(8  + u) * 132 + row] + dsm0b[(8  + u) * 132 + row] + g0v[2];
            float go = dsm0[(12 + u) * 132 + row] + dsm0b[(12 + u) * 132 + row] + g0v[3];
            float cn = c0r * sigm(gf + 1.0f) + sigm(gi) * tanh_(gj);
            c0r = cn;
            float hv = tanh_(cn) * sigm(go);
            unsigned short h16 = bfr(hv);
            *(unsigned short*)(g_h0hi[pW] + eoff) = h16;
            *(unsigned short*)(g_h0lo[pW] + eoff) = bfr(hv - bf2f(h16));
        }
        // ---- L1 epilogue ----
        if (doL1) {
            float gi = dsm1[(0  + u) * 132 + row] + dsm1b[(0  + u) * 132 + row] + bias1s[0  + u];
            float gj = dsm1[(4  + u) * 132 + row] + dsm1b[(4  + u) * 132 + row] + bias1s[4  + u];
            float gf = dsm1[(8  + u) * 132 + row] + dsm1b[(8  + u) * 132 + row] + bias1s[8  + u];
            float go = dsm1[(12 + u) * 132 + row] + dsm1b[(12 + u) * 132 + row] + bias1s[12 + u];
            float cn = c1r * sigm(gf + 1.0f) + sigm(gi) * tanh_(gj);
            c1r = cn;
            float hv = tanh_(cn) * sigm(go);
            unsigned short h16 = bfr(hv);
            *(unsigned short*)(g_h1hi[pA] + eoff) = h16;
            *(unsigned short*)(g_h1lo[pA] + eoff) = bfr(hv - bf2f(h16));
            if (i == Tt) g_h1f[(cell0 + u) * Bb + row] = hv;
        }
        gen++;
        grid_sync(gen);
    }

    // ---- final logits ----
    {
        float s0 = 0.f, s1 = 0.f;
        {
            int n = tid;
            float h = __ldcg(&g_h1f[n * Bb + cta]);
            s0 = h * Wd[n * 2];
            s1 = h * Wd[n * 2 + 1];
        }
        float* red = dsm0;
        float* red2 = dsm1;
        red[tid] = s0; red2[tid] = s1;
        __syncthreads();
        for (int st = 256; st > 0; st >>= 1) {
            if (tid < st) {
                red[tid] += red[tid + st];
                red2[tid] += red2[tid + st];
            }
            __syncthreads();
        }
        if (tid == 0) {
            out[cta * 2]     = red[0]  + bd[0];
            out[cta * 2 + 1] = red2[0] + bd[1];
        }
    }
}

// ---------------- launch ----------------
extern "C" void kernel_launch(void* const* d_in, const int* in_sizes, int n_in,
                              void* d_out, int out_size)
{
    const void*  x   = d_in[0];
    const float* emb = (const float*)d_in[1];
    const float* W0  = (const float*)d_in[2];
    const float* b0  = (const float*)d_in[3];
    const float* W1  = (const float*)d_in[4];
    const float* b1  = (const float*)d_in[5];
    const float* Wd  = (const float*)d_in[6];
    const float* bd  = (const float*)d_in[7];
    float* out = (float*)d_out;
    (void)in_sizes; (void)n_in; (void)out_size;

    static int init_done = 0;
    if (!init_done) {
        cudaFuncSetAttribute(lstm_mma, cudaFuncAttributeMaxDynamicSharedMemorySize, SMEM_BYTES);
        cudaFuncSetAttribute(gemm_in_mma, cudaFuncAttributeMaxDynamicSharedMemorySize, GI_SMEM_BYTES);
        init_done = 1;
    }

    detect_kernel<<<1, 1>>>(x);
    reset_kernel<<<1, 1>>>();

    gemm_in_mma<<<dim3(16, 256), 512, GI_SMEM_BYTES>>>(x, emb, W0, b0);

    lstm_mma<<<NCTA, 512, SMEM_BYTES>>>(W0, W1, b1, Wd, bd, out);
}

// round 13
// speedup vs baseline: 1.4936x; 1.4936x over previous
#include <cuda_runtime.h>
#include <cuda_bf16.h>

#define Bb 128
#define Tt 256
#define Hh 512
#define Ee 300
#define Vv 50000
#define FH 2048
#define NCTA 128

// lstm smem offsets
#define W0F_OFF 0
#define W1F_OFF 32768
#define DSM0_OFF 98304
#define DSM1_OFF 106752
#define DSM0B_OFF 115264
#define DSM1B_OFF 123712
#define BIAS_OFF 132160
#define SMEM_BYTES 132224

// gemm_in smem offsets
#define GI_ROWS_OFF 0
#define GI_WF_OFF 1024
#define GI_DSM_OFF 66560
#define GI_SMEM_BYTES 100352

// ---------------- globals ----------------
__device__ float g_G0in[(size_t)Tt * FH * Bb];   // [t][gatecol][b]
// h planes in A-fragment layout (validated R6/R7):
//   uint4 idx = kt*256 + wm*32 + lane; row=wm*16+(lane>>2), kp=kt*8+(lane&3)
__device__ __align__(16) unsigned char g_h0hi[2][131072];
__device__ __align__(16) unsigned char g_h0lo[2][131072];
__device__ __align__(16) unsigned char g_h1hi[2][131072];
__device__ __align__(16) unsigned char g_h1lo[2][131072];
__device__ float g_h1f[Hh * Bb];
__device__ int g_x64;
__device__ unsigned g_slots[NCTA];
__device__ volatile unsigned g_rel;

// ---------------- helpers ----------------
__device__ __forceinline__ float ex2f(float x) { float y; asm("ex2.approx.f32 %0, %1;" : "=f"(y) : "f"(x)); return y; }
__device__ __forceinline__ float rcpf(float x) { float y; asm("rcp.approx.f32 %0, %1;" : "=f"(y) : "f"(x)); return y; }
__device__ __forceinline__ float sigm(float x) { return rcpf(1.0f + ex2f(-1.4426950408889634f * x)); }
__device__ __forceinline__ float tanh_(float x) { return fmaf(2.0f, sigm(2.0f * x), -1.0f); }
__device__ __forceinline__ unsigned short bfr(float f) {
    unsigned short u; asm("cvt.rn.bf16.f32 %0, %1;" : "=h"(u) : "f"(f)); return u;
}
__device__ __forceinline__ float bf2f(unsigned short u) {
    return __uint_as_float((unsigned)u << 16);
}
// split two floats into packed-bf16 hi and lo planes
__device__ __forceinline__ void split2(float a, float b, unsigned& hi, unsigned& lo) {
    unsigned short ha = bfr(a), hb = bfr(b);
    hi = (unsigned)ha | ((unsigned)hb << 16);
    lo = (unsigned)bfr(a - bf2f(ha)) | ((unsigned)bfr(b - bf2f(hb)) << 16);
}

__device__ __forceinline__ void mma_bf16(float d[4], const uint4& a, unsigned b0, unsigned b1) {
    asm volatile("mma.sync.aligned.m16n8k16.row.col.f32.bf16.bf16.f32 "
        "{%0,%1,%2,%3}, {%4,%5,%6,%7}, {%8,%9}, {%0,%1,%2,%3};"
        : "+f"(d[0]), "+f"(d[1]), "+f"(d[2]), "+f"(d[3])
        : "r"(a.x), "r"(a.y), "r"(a.z), "r"(a.w), "r"(b0), "r"(b1));
}

// slot barrier (validated R8/R9): parallel arrivals, CTA0 collects, single release.
// nanosleep in the spin loops reduces spin power (DVFS headroom) at bounded latency cost.
__device__ __forceinline__ void grid_sync(unsigned gen) {
    __syncthreads();
    if (threadIdx.x == 0) {
        __threadfence();
        ((volatile unsigned*)g_slots)[blockIdx.x] = gen;
    }
    if (blockIdx.x == 0) {
        if (threadIdx.x < NCTA) {
            while (((volatile unsigned*)g_slots)[threadIdx.x] < gen) { __nanosleep(32); }
            __threadfence();
        }
        __syncthreads();
        if (threadIdx.x == 0) g_rel = gen;
    } else {
        if (threadIdx.x == 0) {
            while (g_rel < gen) { __nanosleep(32); }
            __threadfence();
        }
    }
    __syncthreads();
}

// ---------------- detect + reset (merged, one launch) ----------------
__global__ void detect_kernel(const void* x) {
    const long long* p = (const long long*)x;
    int ok64 = 1;
    for (int i = 0; i < 16; i++) { long long v = p[i]; if (v < 0 || v >= Vv) ok64 = 0; }
    g_x64 = ok64;
    for (int i = 0; i < NCTA; i++) g_slots[i] = 0;
    g_rel = 0;
}
__device__ __forceinline__ int token_at(const void* x, int idx) {
    if (g_x64) return (int)((const long long*)x)[idx];
    return ((const int*)x)[idx];
}

// ---------------- G0in precompute: warp-MMA bf16 3-term (validated R9) ----------------
__global__ void __launch_bounds__(512) gemm_in_mma(
    const void* __restrict__ x, const float* __restrict__ emb,
    const float* __restrict__ W0, const float* __restrict__ b0)
{
    extern __shared__ char smg[];
    int* rows = (int*)(smg + GI_ROWS_OFF);
    uint4* wf = (uint4*)(smg + GI_WF_OFF);
    float* dsmA = (float*)(smg + GI_DSM_OFF);
    float* dsmB = (float*)(smg + GI_DSM_OFF + 16896);

    const int tid = threadIdx.x;
    const int bx = blockIdx.x;
    const int t = blockIdx.y;
    const int wid = tid >> 5;
    const int lane = tid & 31;
    const int wm = wid & 7;
    const int nh = wid >> 3;

    if (tid < 128) rows[tid] = token_at(x, tid * Tt + t);

    auto build_w = [&](int kc, int buf) {
        int nkt = (kc == 4) ? 3 : 4;
        uint4* dst = wf + buf * 2048;
        for (int e = tid; e < nkt * 512; e += 512) {
            int j = e >> 9, cg = (e >> 5) & 15, ln = e & 31;
            int col = bx * 128 + cg * 8 + (ln >> 2);
            int k = (kc * 4 + j) * 16 + (ln & 3) * 2;
            float v0 = (k     < Ee) ? W0[(size_t)k * FH + col]       : 0.f;
            float v1 = (k + 1 < Ee) ? W0[(size_t)(k + 1) * FH + col] : 0.f;
            float v8 = (k + 8 < Ee) ? W0[(size_t)(k + 8) * FH + col] : 0.f;
            float v9 = (k + 9 < Ee) ? W0[(size_t)(k + 9) * FH + col] : 0.f;
            unsigned h01, l01, h89, l89;
            split2(v0, v1, h01, l01);
            split2(v8, v9, h89, l89);
            dst[(j * 16 + cg) * 32 + ln] = make_uint4(h01, h89, l01, l89);
        }
    };

    __syncthreads();
    build_w(0, 0);
    __syncthreads();

    float d[8][4];
#pragma unroll
    for (int n = 0; n < 8; n++)
#pragma unroll
        for (int q = 0; q < 4; q++) d[n][q] = 0.f;

    const int r1 = wm * 16 + (lane >> 2);
    const int r2 = r1 + 8;
    const float* e1 = emb + (size_t)rows[r1] * Ee;
    const float* e2 = emb + (size_t)rows[r2] * Ee;

    for (int kc = 0; kc < 5; kc++) {
        int nkt = (kc == 4) ? 3 : 4;
        uint4 Ah[4], Al[4];
        for (int j = 0; j < nkt; j++) {
            int k = (kc * 4 + j) * 16 + (lane & 3) * 2;
            float a0 = (k     < Ee) ? e1[k]     : 0.f;
            float a1 = (k + 1 < Ee) ? e1[k + 1] : 0.f;
            float b0v = (k     < Ee) ? e2[k]     : 0.f;
            float b1v = (k + 1 < Ee) ? e2[k + 1] : 0.f;
            float c0 = (k + 8 < Ee) ? e1[k + 8] : 0.f;
            float c1 = (k + 9 < Ee) ? e1[k + 9] : 0.f;
            float f0 = (k + 8 < Ee) ? e2[k + 8] : 0.f;
            float f1 = (k + 9 < Ee) ? e2[k + 9] : 0.f;
            unsigned xh, xl, yh, yl, zh, zl, wh, wl;
            split2(a0, a1, xh, xl);
            split2(b0v, b1v, yh, yl);
            split2(c0, c1, zh, zl);
            split2(f0, f1, wh, wl);
            Ah[j] = make_uint4(xh, yh, zh, wh);
            Al[j] = make_uint4(xl, yl, zl, wl);
        }
        const uint4* wcur = wf + (kc & 1) * 2048;
        for (int j = 0; j < nkt; j++) {
#pragma unroll
            for (int nt = 0; nt < 8; nt++) {
                uint4 w = wcur[(j * 16 + nh * 8 + nt) * 32 + lane];
                mma_bf16(d[nt], Ah[j], w.x, w.y);
                mma_bf16(d[nt], Al[j], w.x, w.y);
                mma_bf16(d[nt], Ah[j], w.z, w.w);
            }
        }
        if (kc < 4) build_w(kc + 1, (kc + 1) & 1);
        __syncthreads();
    }

    const int r0 = wm * 16 + (lane >> 2);
    for (int p = 0; p < 2; p++) {
        float* mybuf = nh ? dsmB : dsmA;
#pragma unroll
        for (int q = 0; q < 4; q++) {
            int nt = p * 4 + q;
            int lc = q * 8 + (lane & 3) * 2;
            mybuf[lc * 132 + r0]           = d[nt][0];
            mybuf[(lc + 1) * 132 + r0]     = d[nt][1];
            mybuf[lc * 132 + r0 + 8]       = d[nt][2];
            mybuf[(lc + 1) * 132 + r0 + 8] = d[nt][3];
        }
        __syncthreads();
#pragma unroll
        for (int it = 0; it < 16; it++) {
            int e = it * 512 + tid;
            int col64 = e >> 7, row = e & 127;
            int half = col64 >> 5, c5 = col64 & 31;
            int gcol = bx * 128 + half * 64 + p * 32 + c5;
            float v = (half ? dsmB : dsmA)[c5 * 132 + row] + b0[gcol];
            g_G0in[((size_t)t * FH + gcol) * Bb + row] = v;
        }
        __syncthreads();
    }
}

// ---------------- persistent warp-MMA LSTM (exact R9 structure) ----------------
__global__ void __launch_bounds__(512, 1) lstm_mma(
    const float* __restrict__ W0, const float* __restrict__ W1,
    const float* __restrict__ b1, const float* __restrict__ Wd,
    const float* __restrict__ bd, float* __restrict__ out)
{
    extern __shared__ char smc[];
    uint4* w0f = (uint4*)(smc + W0F_OFF);
    uint4* w1f = (uint4*)(smc + W1F_OFF);
    float* dsm0 = (float*)(smc + DSM0_OFF);
    float* dsm1 = (float*)(smc + DSM1_OFF);
    float* dsm0b = (float*)(smc + DSM0B_OFF);
    float* dsm1b = (float*)(smc + DSM1B_OFF);
    float* bias1s = (float*)(smc + BIAS_OFF);

    const int tid = threadIdx.x;
    const int cta = blockIdx.x;
    const int cell0 = cta * 4;
    const int wid = tid >> 5;
    const int lane = tid & 31;
    const int kh = wid >> 3;
    const int wm = wid & 7;

    // ---- build W fragments (once; validated) ----
    for (int idx = tid; idx < 2048; idx += 512) {
        int kt = idx >> 6, nt = (idx >> 5) & 1, ln = idx & 31;
        int col = nt * 8 + (ln >> 2);
        int gcol = (col >> 2) * 512 + cell0 + (col & 3);
        int kb = kt * 16 + (ln & 3) * 2;
        float v0 = W0[(size_t)(Ee + kb) * FH + gcol];
        float v1 = W0[(size_t)(Ee + kb + 1) * FH + gcol];
        float v8 = W0[(size_t)(Ee + kb + 8) * FH + gcol];
        float v9 = W0[(size_t)(Ee + kb + 9) * FH + gcol];
        unsigned h01, l01, h89, l89;
        split2(v0, v1, h01, l01);
        split2(v8, v9, h89, l89);
        w0f[idx] = make_uint4(h01, h89, l01, l89);
    }
    for (int idx = tid; idx < 4096; idx += 512) {
        int kt = idx >> 6, nt = (idx >> 5) & 1, ln = idx & 31;
        int col = nt * 8 + (ln >> 2);
        int gcol = (col >> 2) * 512 + cell0 + (col & 3);
        int kb = kt * 16 + (ln & 3) * 2;
        float v0 = W1[(size_t)kb * FH + gcol];
        float v1 = W1[(size_t)(kb + 1) * FH + gcol];
        float v8 = W1[(size_t)(kb + 8) * FH + gcol];
        float v9 = W1[(size_t)(kb + 9) * FH + gcol];
        unsigned h01, l01, h89, l89;
        split2(v0, v1, h01, l01);
        split2(v8, v9, h89, l89);
        w1f[idx] = make_uint4(h01, h89, l01, l89);
    }
    if (tid < 16) bias1s[tid] = b1[(tid >> 2) * 512 + cell0 + (tid & 3)];

    {
        int o = cta * 512 + tid;
        if (o < 8192) {
            uint4 z = make_uint4(0, 0, 0, 0);
            ((uint4*)g_h0hi[1])[o] = z; ((uint4*)g_h0lo[1])[o] = z;
            ((uint4*)g_h1hi[1])[o] = z; ((uint4*)g_h1lo[1])[o] = z;
        }
    }
    unsigned gen = 1;
    grid_sync(gen);

    // epilogue mapping (validated R7)
    const int row = tid & 127;
    const int u = tid >> 7;
    const int kp_g = (cell0 + u) >> 1;
    const int half = u & 1;
    const int kt_e = kp_g >> 3, kpi = kp_g & 7;
    const int rr = row & 15;
    const unsigned eoff = (unsigned)(kt_e * 4096 + (row >> 4) * 512 +
                          (((rr & 7) << 2) | (kpi & 3)) * 16 +
                          ((kpi >= 4 ? 2 : 0) + (rr >= 8 ? 1 : 0)) * 4 + half * 2);
    float c0r = 0.f, c1r = 0.f;

    const unsigned fbase = wm * 32 + lane;
    const unsigned kbase = kh * 16;

    for (int i = 0; i <= Tt; i++) {
        const int pA = (i + 1) & 1;
        const int pW = i & 1;
        const bool doL0 = (i < Tt);
        const bool doL1 = (i > 0);

        float g0v[4];
        if (doL0) {
#pragma unroll
            for (int g = 0; g < 4; g++)
                g0v[g] = __ldcg(&g_G0in[((size_t)i * FH + g * 512 + cell0 + u) * Bb + row]);
        }

        float d0[2][4], d1[2][4];
#pragma unroll
        for (int n = 0; n < 2; n++)
#pragma unroll
            for (int q = 0; q < 4; q++) { d0[n][q] = 0.f; d1[n][q] = 0.f; }

        // ---- pass 1: A = h0(i-1) K-half; 4-kt bursts (validated R8) ----
        {
            const uint4* ah = (const uint4*)g_h0hi[pA];
            const uint4* al = (const uint4*)g_h0lo[pA];
            uint4 A[2][4], L[2][4];
#pragma unroll
            for (int j = 0; j < 4; j++) {
                A[0][j] = __ldcg(ah + (kbase + j) * 256 + fbase);
                L[0][j] = __ldcg(al + (kbase + j) * 256 + fbase);
            }
#pragma unroll
            for (int kb = 0; kb < 4; kb++) {
                const int cur = kb & 1, nxt = cur ^ 1;
                if (kb < 3) {
#pragma unroll
                    for (int j = 0; j < 4; j++) {
                        A[nxt][j] = __ldcg(ah + (kbase + (kb + 1) * 4 + j) * 256 + fbase);
                        L[nxt][j] = __ldcg(al + (kbase + (kb + 1) * 4 + j) * 256 + fbase);
                    }
                }
#pragma unroll
                for (int j = 0; j < 4; j++) {
                    const int kt = kbase + kb * 4 + j;
#pragma unroll
                    for (int nt = 0; nt < 2; nt++) {
                        if (doL0) {
                            uint4 w = w0f[(kt * 2 + nt) * 32 + lane];
                            mma_bf16(d0[nt], A[cur][j], w.x, w.y);
                            mma_bf16(d0[nt], L[cur][j], w.x, w.y);
                            mma_bf16(d0[nt], A[cur][j], w.z, w.w);
                        }
                        if (doL1) {
                            uint4 w = w1f[(kt * 2 + nt) * 32 + lane];
                            mma_bf16(d1[nt], A[cur][j], w.x, w.y);
                            mma_bf16(d1[nt], L[cur][j], w.x, w.y);
                            mma_bf16(d1[nt], A[cur][j], w.z, w.w);
                        }
                    }
                }
            }
        }
        // ---- pass 2: A = h1(i-2) K-half ----
        if (doL1) {
            const uint4* ah = (const uint4*)g_h1hi[pW];
            const uint4* al = (const uint4*)g_h1lo[pW];
            uint4 A[2][4], L[2][4];
#pragma unroll
            for (int j = 0; j < 4; j++) {
                A[0][j] = __ldcg(ah + (kbase + j) * 256 + fbase);
                L[0][j] = __ldcg(al + (kbase + j) * 256 + fbase);
            }
#pragma unroll
            for (int kb = 0; kb < 4; kb++) {
                const int cur = kb & 1, nxt = cur ^ 1;
                if (kb < 3) {
#pragma unroll
                    for (int j = 0; j < 4; j++) {
                        A[nxt][j] = __ldcg(ah + (kbase + (kb + 1) * 4 + j) * 256 + fbase);
                        L[nxt][j] = __ldcg(al + (kbase + (kb + 1) * 4 + j) * 256 + fbase);
                    }
                }
#pragma unroll
                for (int j = 0; j < 4; j++) {
                    const int kt = kbase + kb * 4 + j;
#pragma unroll
                    for (int nt = 0; nt < 2; nt++) {
                        uint4 w = w1f[((32 + kt) * 2 + nt) * 32 + lane];
                        mma_bf16(d1[nt], A[cur][j], w.x, w.y);
                        mma_bf16(d1[nt], L[cur][j], w.x, w.y);
                        mma_bf16(d1[nt], A[cur][j], w.z, w.w);
                    }
                }
            }
        }

        // ---- combine: each K-half writes its OWN buffers; ONE sync (validated R9) ----
        {
            int r0 = wm * 16 + (lane >> 2);
            float* b0p = kh ? dsm0b : dsm0;
            float* b1p = kh ? dsm1b : dsm1;
#pragma unroll
            for (int nt = 0; nt < 2; nt++) {
                int c = nt * 8 + (lane & 3) * 2;
                b0p[c * 132 + r0]           = d0[nt][0];
                b0p[(c + 1) * 132 + r0]     = d0[nt][1];
                b0p[c * 132 + r0 + 8]       = d0[nt][2];
                b0p[(c + 1) * 132 + r0 + 8] = d0[nt][3];
                b1p[c * 132 + r0]           = d1[nt][0];
                b1p[(c + 1) * 132 + r0]     = d1[nt][1];
                b1p[c * 132 + r0 + 8]       = d1[nt][2];
                b1p[(c + 1) * 132 + r0 + 8] = d1[nt][3];
            }
        }
        __syncthreads();

        // ---- L0 epilogue ----
        if (doL0) {
            float gi = dsm0[(0  + u) * 132 + row] + dsm0b[(0  + u) * 132 + row] + g0v[0];
            float gj = dsm0[(4  + u) * 132 + row] + dsm0b[(4  + u) * 132 + row] + g0v[1];
            float gf = dsm0[(8  + u) * 132 + row] + dsm0b[(8  + u) * 132 + row] + g0v[2];
            float go = dsm0[(12 + u) * 132 + row] + dsm0b[(12 + u) * 132 + row] + g0v[3];
            float cn = c0r * sigm(gf + 1.0f) + sigm(gi) * tanh_(gj);
            c0r = cn;
            float hv = tanh_(cn) * sigm(go);
            unsigned short h16 = bfr(hv);
            *(unsigned short*)(g_h0hi[pW] + eoff) = h16;
            *(unsigned short*)(g_h0lo[pW] + eoff) = bfr(hv - bf2f(h16));
        }
        // ---- L1 epilogue ----
        if (doL1) {
            float gi = dsm1[(0  + u) * 132 + row] + dsm1b[(0  + u) * 132 + row] + bias1s[0  + u];
            float gj = dsm1[(4  + u) * 132 + row] + dsm1b[(4  + u) * 132 + row] + bias1s[4  + u];
            float gf = dsm1[(8  + u) * 132 + row] + dsm1b[(8  + u) * 132 + row] + bias1s[8  + u];
            float go = dsm1[(12 + u) * 132 + row] + dsm1b[(12 + u) * 132 + row] + bias1s[12 + u];
            float cn = c1r * sigm(gf + 1.0f) + sigm(gi) * tanh_(gj);
            c1r = cn;
            float hv = tanh_(cn) * sigm(go);
            unsigned short h16 = bfr(hv);
            *(unsigned short*)(g_h1hi[pA] + eoff) = h16;
            *(unsigned short*)(g_h1lo[pA] + eoff) = bfr(hv - bf2f(h16));
            if (i == Tt) g_h1f[(cell0 + u) * Bb + row] = hv;
        }
        gen++;
        grid_sync(gen);
    }

    // ---- final logits ----
    {
        float s0 = 0.f, s1 = 0.f;
        {
            int n = tid;
            float h = __ldcg(&g_h1f[n * Bb + cta]);
            s0 = h * Wd[n * 2];
            s1 = h * Wd[n * 2 + 1];
        }
        float* red = dsm0;
        float* red2 = dsm1;
        red[tid] = s0; red2[tid] = s1;
        __syncthreads();
        for (int st = 256; st > 0; st >>= 1) {
            if (tid < st) {
                red[tid] += red[tid + st];
                red2[tid] += red2[tid + st];
            }
            __syncthreads();
        }
        if (tid == 0) {
            out[cta * 2]     = red[0]  + bd[0];
            out[cta * 2 + 1] = red2[0] + bd[1];
        }
    }
}

// ---------------- launch ----------------
extern "C" void kernel_launch(void* const* d_in, const int* in_sizes, int n_in,
                              void* d_out, int out_size)
{
    const void*  x   = d_in[0];
    const float* emb = (const float*)d_in[1];
    const float* W0  = (const float*)d_in[2];
    const float* b0  = (const float*)d_in[3];
    const float* W1  = (const float*)d_in[4];
    const float* b1  = (const float*)d_in[5];
    const float* Wd  = (const float*)d_in[6];
    const float* bd  = (const float*)d_in[7];
    float* out = (float*)d_out;
    (void)in_sizes; (void)n_in; (void)out_size;

    static int init_done = 0;
    if (!init_done) {
        cudaFuncSetAttribute(lstm_mma, cudaFuncAttributeMaxDynamicSharedMemorySize, SMEM_BYTES);
        cudaFuncSetAttribute(gemm_in_mma, cudaFuncAttributeMaxDynamicSharedMemorySize, GI_SMEM_BYTES);
        init_done = 1;
    }

    detect_kernel<<<1, 1>>>(x);

    gemm_in_mma<<<dim3(16, 256), 512, GI_SMEM_BYTES>>>(x, emb, W0, b0);

    lstm_mma<<<NCTA, 512, SMEM_BYTES>>>(W0, W1, b1, Wd, bd, out);
}